// round 17
// baseline (speedup 1.0000x reference)
#include <cuda_runtime.h>
#include <cuda_bf16.h>
#include <cuda_fp16.h>
#include <math.h>
#include <stdint.h>

#define R_TOT 16384
#define S_LEN 4096
#define D_DIM 128
#define K_LNK 13
#define M_NET 12
#define F8_SCALE 256.0f
#define F8_INV   0.00390625f

typedef unsigned int u32;
typedef unsigned short u16;
typedef unsigned char u8;
typedef unsigned long long u64;

// ---------------- scratch (static device memory only) ----------------------
__device__ __nv_bfloat16 g_Xhi[R_TOT * D_DIM];          // X hi, row-major
__device__ __nv_bfloat16 g_Xlo[R_TOT * D_DIM];          // X lo
__device__ __nv_bfloat16 g_B1hi[13 * 128 * 128];        // W1^T [net][n][k]
__device__ __nv_bfloat16 g_B1lo[13 * 128 * 128];
__device__ __nv_bfloat16 g_B2ghi[128 * 128];            // gW2^T [n][k]
__device__ __nv_bfloat16 g_B2glo[128 * 128];
__device__ __nv_bfloat16 g_B2fhi[12 * 16 * 128];        // fW2^T padded N=16
__device__ float g_Vres[R_TOT * D_DIM];                 // fp32 residual (exact)
__device__ u8    g_Vf8r[R_TOT * D_DIM];                 // fp8 residual seed (*256)
__device__ u8    g_Vf8a[R_TOT * D_DIM];                 // fp8 V pong (*256)
__device__ u8    g_Vf8b[R_TOT * D_DIM];                 // fp8 V ping (*256)
__device__ float g_Wall[M_NET * R_TOT * K_LNK];

// ---------------- helpers ---------------------------------------------------
__device__ __forceinline__ u32 smem_u32(const void* p) {
    u32 a;
    asm("{ .reg .u64 t; cvta.to.shared.u64 t, %1; cvt.u32.u64 %0, t; }"
        : "=r"(a) : "l"(p));
    return a;
}
__device__ __forceinline__ void ldsm4(u32* r, u32 addr) {
    asm volatile("ldmatrix.sync.aligned.m8n8.x4.shared.b16 {%0,%1,%2,%3}, [%4];"
        : "=r"(r[0]), "=r"(r[1]), "=r"(r[2]), "=r"(r[3]) : "r"(addr));
}
__device__ __forceinline__ void mma16816(float* d, const u32* a, const u32* b) {
    asm volatile(
        "mma.sync.aligned.m16n8k16.row.col.f32.bf16.bf16.f32 "
        "{%0,%1,%2,%3}, {%4,%5,%6,%7}, {%8,%9}, {%0,%1,%2,%3};"
        : "+f"(d[0]), "+f"(d[1]), "+f"(d[2]), "+f"(d[3])
        : "r"(a[0]), "r"(a[1]), "r"(a[2]), "r"(a[3]), "r"(b[0]), "r"(b[1]));
}
// swizzled byte address of 16B unit (r, c16) in a [rows][128]bf16 smem tile
__device__ __forceinline__ u32 sw_addr(u32 base, int r, int c16) {
    return base + (u32)(((r << 4) + (c16 ^ (r & 7))) << 4);
}
__device__ __forceinline__ void bf_split(float v, u16& h, u16& l) {
    __nv_bfloat16 hb = __float2bfloat16(v);
    __nv_bfloat16 lb = __float2bfloat16(v - __bfloat162float(hb));
    h = __bfloat16_as_ushort(hb);
    l = __bfloat16_as_ushort(lb);
}
// pack two fp32 -> bf16x2 (lo arg in low half = memory-first element)
__device__ __forceinline__ u32 pack_bf16x2(float lo, float hi) {
    u32 r;
    asm("cvt.rn.bf16x2.f32 %0, %1, %2;" : "=r"(r) : "f"(hi), "f"(lo));
    return r;
}
// pack two fp32 -> f16x2 (lo arg in low half)
__device__ __forceinline__ u32 f32_to_h2(float lo, float hi) {
    u32 r;
    asm("cvt.rn.f16x2.f32 %0, %1, %2;" : "=r"(r) : "f"(hi), "f"(lo));
    return r;
}
// 4 packed e4m3 (u32) -> two f16x2
__device__ __forceinline__ void f8_to_h2(u32 p, u32& a, u32& b) {
    u16 lo, hi;
    asm("mov.b32 {%0,%1}, %2;" : "=h"(lo), "=h"(hi) : "r"(p));
    asm("cvt.rn.f16x2.e4m3x2 %0, %1;" : "=r"(a) : "h"(lo));
    asm("cvt.rn.f16x2.e4m3x2 %0, %1;" : "=r"(b) : "h"(hi));
}
// f16x2 -> 2 packed e4m3
__device__ __forceinline__ u16 h2_to_f8(u32 h2) {
    u16 r;
    asm("cvt.rn.satfinite.e4m3x2.f16x2 %0, %1;" : "=h"(r) : "r"(h2));
    return r;
}
__device__ __forceinline__ u32 pack_u16x2(u16 a, u16 b) {
    u32 r;
    asm("mov.b32 %0, {%1,%2};" : "=r"(r) : "h"(a), "h"(b));
    return r;
}
__device__ __forceinline__ void hfma2(u32& d, u32 a, u32 b) {
    asm("fma.rn.f16x2 %0, %1, %2, %0;" : "+r"(d) : "r"(a), "r"(b));
}
__device__ __forceinline__ u32 hadd2(u32 a, u32 b) {
    u32 r;
    asm("add.rn.f16x2 %0, %1, %2;" : "=r"(r) : "r"(a), "r"(b));
    return r;
}
__device__ __forceinline__ float gelu_exact(float x) {
    return 0.5f * x * (1.0f + erff(x * 0.70710678118654752440f));
}

// ---------------------------------------------------------------------------
// k_init: weight prep + embeddings.
//  blocks [0..12]  : W1 transpose+split per net (smem 32x32 tiles, coalesced)
//  block  [13]     : gW2 transpose+split
//  blocks [14..61] : fW2 prep (small)
//  blocks [62.. )  : embeddings
// ---------------------------------------------------------------------------
#define PREP_C (12 * 16 * 64)
#define C_BLK  ((PREP_C + 255) / 256)          // 48
#define EMB_TOT (R_TOT * 16)
#define EMB_BLK (EMB_TOT / 256)                // 1024
#define INIT_BLK (14 + C_BLK + EMB_BLK)

__global__ void k_init(const float* __restrict__ gW1,
                       const float* __restrict__ gW2,
                       const float* __restrict__ fW1,
                       const float* __restrict__ fW2,
                       const int* __restrict__ data,
                       const float* __restrict__ emb,
                       const float* __restrict__ apc) {
    const int tid = threadIdx.x;
    if (blockIdx.x < 14) {
        // ---- 128x128 transpose + bf16 split, coalesced both ways ----
        const int net = blockIdx.x;            // 0..12 = W1 nets (0 = g), 13 = gW2
        const float* src = (net == 0) ? gW1
                         : (net == 13) ? gW2
                         : fW1 + (size_t)(net - 1) * 128 * 128;
        u32* dh = (net == 13) ? (u32*)g_B2ghi : (u32*)g_B1hi + net * 8192;
        u32* dl = (net == 13) ? (u32*)g_B2glo : (u32*)g_B1lo + net * 8192;

        __shared__ float ts[32][33];
        const int tx = tid & 31, ty = tid >> 5;          // 32 x 8
        for (int tile = 0; tile < 16; ++tile) {
            const int ti = tile >> 2, tj = tile & 3;     // ti: k-tile, tj: n-tile
            #pragma unroll
            for (int p = 0; p < 4; ++p) {
                int k = ti * 32 + ty + p * 8;
                ts[ty + p * 8][tx] = src[k * 128 + tj * 32 + tx];
            }
            __syncthreads();
            #pragma unroll
            for (int p = 0; p < 2; ++p) {
                int slot = tid + p * 256;
                int x = slot & 15, y = slot >> 4;        // x: k-pair, y: n
                float w0 = ts[2 * x][y], w1 = ts[2 * x + 1][y];
                u16 h0, l0, h1, l1;
                bf_split(w0, h0, l0); bf_split(w1, h1, l1);
                int widx = (tj * 32 + y) * 64 + ti * 16 + x;
                dh[widx] = (u32)h0 | ((u32)h1 << 16);
                dl[widx] = (u32)l0 | ((u32)l1 << 16);
            }
            __syncthreads();
        }
    } else if (blockIdx.x < 14 + C_BLK) {
        int r = (blockIdx.x - 14) * 256 + tid;
        if (r >= PREP_C) return;
        int net = r >> 10;
        int rr = r & 1023;
        int n = rr >> 6, k = (rr & 63) * 2;
        float w0 = (n < 13) ? fW2[(size_t)net * 128 * 13 + k * 13 + n] : 0.0f;
        float w1 = (n < 13) ? fW2[(size_t)net * 128 * 13 + (k + 1) * 13 + n] : 0.0f;
        ((u32*)g_B2fhi)[(net * 16 + n) * 64 + (k >> 1)] = pack_bf16x2(w0, w1);
    } else {
        int idx = (blockIdx.x - 14 - C_BLK) * 256 + tid;
        int row = idx >> 4;
        int g8 = idx & 15;
        int tok = data[row];
        int s = row & (S_LEN - 1);
        float4 e0 = ((const float4*)emb)[tok * 32 + g8 * 2];
        float4 e1 = ((const float4*)emb)[tok * 32 + g8 * 2 + 1];
        float4 a0 = ((const float4*)apc)[s * 32 + g8 * 2];
        float4 a1 = ((const float4*)apc)[s * 32 + g8 * 2 + 1];
        float v[8] = {e0.x + a0.x, e0.y + a0.y, e0.z + a0.z, e0.w + a0.w,
                      e1.x + a1.x, e1.y + a1.y, e1.z + a1.z, e1.w + a1.w};
        u32 hp[4], lp[4];
        #pragma unroll
        for (int p = 0; p < 4; ++p) {
            u16 h0, l0, h1, l1;
            bf_split(v[2 * p], h0, l0);
            bf_split(v[2 * p + 1], h1, l1);
            hp[p] = (u32)h0 | ((u32)h1 << 16);
            lp[p] = (u32)l0 | ((u32)l1 << 16);
        }
        ((uint4*)g_Xhi)[row * 16 + g8] = make_uint4(hp[0], hp[1], hp[2], hp[3]);
        ((uint4*)g_Xlo)[row * 16 + g8] = make_uint4(lp[0], lp[1], lp[2], lp[3]);
    }
}

// ---------------------------------------------------------------------------
// k_mlp_g: g-net only (3-term bf16 hi/lo split, fp32 backbone).
// grid = 128 row-tiles, 512 threads, 132 KB smem (1 CTA/SM).
// ---------------------------------------------------------------------------
#define G_W1HI  0
#define G_W1LO  32768
#define G_XHHI  65536
#define G_XHLO  98304
#define G_B1S   131072
#define G_B2S   131584
#define SMEM_G  132096

extern __shared__ char smc[];

__global__ void __launch_bounds__(512, 1) k_mlp_g(
    const float* __restrict__ gb1, const float* __restrict__ gb2) {
    const int tid = threadIdx.x;
    const int lane = tid & 31;
    const int wid = tid >> 5;
    const int row0 = blockIdx.x * 128;
    const u32 sbase = smem_u32(smc);
    float* b1s = (float*)(smc + G_B1S);
    float* b2s = (float*)(smc + G_B2S);

    {
        const uint4* s1h = (const uint4*)g_B1hi;
        const uint4* s1l = (const uint4*)g_B1lo;
        const uint4* sxh = (const uint4*)g_Xhi + row0 * 16;
        const uint4* sxl = (const uint4*)g_Xlo + row0 * 16;
        #pragma unroll
        for (int p = 0; p < 4; ++p) {
            int q = tid + p * 512;
            int r = q >> 4, c16 = q & 15;
            u32 d = (u32)(((r << 4) + (c16 ^ (r & 7))) << 4);
            *(uint4*)(smc + G_W1HI + d) = s1h[q];
            *(uint4*)(smc + G_W1LO + d) = s1l[q];
            *(uint4*)(smc + G_XHHI + d) = sxh[q];
            *(uint4*)(smc + G_XHLO + d) = sxl[q];
        }
    }
    if (tid < 128) { b1s[tid] = gb1[tid]; b2s[tid] = gb2[tid]; }
    __syncthreads();

    const int a_ro = (lane & 7) + (lane & 8);
    const int a_co = lane >> 4;
    const int b_ro = (lane & 7) + ((lane >> 1) & 8);
    const int b_co = (lane >> 3) & 1;
    const int tq = lane >> 2;
    const int tr = (lane & 3) * 2;
    const int wm = (wid & 3) * 32;
    const int wn = (wid >> 2) * 32;

    // Layer 1 (3-term split)
    float acc[2][4][4];
    #pragma unroll
    for (int i = 0; i < 2; ++i)
        #pragma unroll
        for (int j = 0; j < 4; ++j)
            #pragma unroll
            for (int q = 0; q < 4; ++q) acc[i][j][q] = 0.0f;

    #pragma unroll
    for (int k = 0; k < 8; ++k) {
        const int kc = k * 2;
        u32 ah[2][4], al[2][4], bh[2][4], bl[2][4];
        #pragma unroll
        for (int mt = 0; mt < 2; ++mt) {
            int r = wm + mt * 16 + a_ro;
            ldsm4(ah[mt], sw_addr(sbase + G_XHHI, r, kc + a_co));
            ldsm4(al[mt], sw_addr(sbase + G_XHLO, r, kc + a_co));
        }
        #pragma unroll
        for (int ng = 0; ng < 2; ++ng) {
            int r = wn + ng * 16 + b_ro;
            ldsm4(bh[ng], sw_addr(sbase + G_W1HI, r, kc + b_co));
            ldsm4(bl[ng], sw_addr(sbase + G_W1LO, r, kc + b_co));
        }
        #pragma unroll
        for (int mt = 0; mt < 2; ++mt)
            #pragma unroll
            for (int ng = 0; ng < 2; ++ng) {
                mma16816(acc[mt][2 * ng],     ah[mt], &bh[ng][0]);
                mma16816(acc[mt][2 * ng + 1], ah[mt], &bh[ng][2]);
                mma16816(acc[mt][2 * ng],     ah[mt], &bl[ng][0]);
                mma16816(acc[mt][2 * ng + 1], ah[mt], &bl[ng][2]);
                mma16816(acc[mt][2 * ng],     al[mt], &bh[ng][0]);
                mma16816(acc[mt][2 * ng + 1], al[mt], &bh[ng][2]);
            }
    }
    __syncthreads();

    // epilogue 1: bias + gelu + hi/lo split -> XH regions
    #pragma unroll
    for (int mt = 0; mt < 2; ++mt)
        #pragma unroll
        for (int nt = 0; nt < 4; ++nt) {
            int r = wm + mt * 16 + tq;
            int c = wn + nt * 8 + tr;
            float v0 = gelu_exact(acc[mt][nt][0] + b1s[c]);
            float v1 = gelu_exact(acc[mt][nt][1] + b1s[c + 1]);
            float v2 = gelu_exact(acc[mt][nt][2] + b1s[c]);
            float v3 = gelu_exact(acc[mt][nt][3] + b1s[c + 1]);
            int c16 = c >> 3, cb = (c & 7) * 2;
            u32 d0 = sw_addr(sbase + G_XHHI, r, c16) - sbase + cb;
            u32 d8 = sw_addr(sbase + G_XHHI, r + 8, c16) - sbase + cb;
            u16 h0, l0, h1, l1, h2, l2, h3, l3;
            bf_split(v0, h0, l0); bf_split(v1, h1, l1);
            bf_split(v2, h2, l2); bf_split(v3, h3, l3);
            *(u32*)(smc + d0) = (u32)h0 | ((u32)h1 << 16);
            *(u32*)(smc + d8) = (u32)h2 | ((u32)h3 << 16);
            *(u32*)(smc + d0 + (G_XHLO - G_XHHI)) = (u32)l0 | ((u32)l1 << 16);
            *(u32*)(smc + d8 + (G_XHLO - G_XHHI)) = (u32)l2 | ((u32)l3 << 16);
        }

    // restage gW2^T over W1
    {
        const uint4* s2h = (const uint4*)g_B2ghi;
        const uint4* s2l = (const uint4*)g_B2glo;
        #pragma unroll
        for (int p = 0; p < 4; ++p) {
            int q = tid + p * 512;
            int r = q >> 4, c16 = q & 15;
            u32 d = (u32)(((r << 4) + (c16 ^ (r & 7))) << 4);
            *(uint4*)(smc + G_W1HI + d) = s2h[q];
            *(uint4*)(smc + G_W1LO + d) = s2l[q];
        }
    }
    __syncthreads();

    // Layer 2 (3-term split)
    float ac2[2][4][4];
    #pragma unroll
    for (int i = 0; i < 2; ++i)
        #pragma unroll
        for (int j = 0; j < 4; ++j)
            #pragma unroll
            for (int q = 0; q < 4; ++q) ac2[i][j][q] = 0.0f;
    #pragma unroll
    for (int k = 0; k < 8; ++k) {
        const int kc = k * 2;
        u32 ah[2][4], al[2][4], bh[2][4], bl[2][4];
        #pragma unroll
        for (int mt = 0; mt < 2; ++mt) {
            int r = wm + mt * 16 + a_ro;
            ldsm4(ah[mt], sw_addr(sbase + G_XHHI, r, kc + a_co));
            ldsm4(al[mt], sw_addr(sbase + G_XHLO, r, kc + a_co));
        }
        #pragma unroll
        for (int ng = 0; ng < 2; ++ng) {
            int r = wn + ng * 16 + b_ro;
            ldsm4(bh[ng], sw_addr(sbase + G_W1HI, r, kc + b_co));
            ldsm4(bl[ng], sw_addr(sbase + G_W1LO, r, kc + b_co));
        }
        #pragma unroll
        for (int mt = 0; mt < 2; ++mt)
            #pragma unroll
            for (int ng = 0; ng < 2; ++ng) {
                mma16816(ac2[mt][2 * ng],     ah[mt], &bh[ng][0]);
                mma16816(ac2[mt][2 * ng + 1], ah[mt], &bh[ng][2]);
                mma16816(ac2[mt][2 * ng],     ah[mt], &bl[ng][0]);
                mma16816(ac2[mt][2 * ng + 1], ah[mt], &bl[ng][2]);
                mma16816(ac2[mt][2 * ng],     al[mt], &bh[ng][0]);
                mma16816(ac2[mt][2 * ng + 1], al[mt], &bh[ng][2]);
            }
    }
    #pragma unroll
    for (int mt = 0; mt < 2; ++mt)
        #pragma unroll
        for (int nt = 0; nt < 4; ++nt) {
            int r = wm + mt * 16 + tq;
            int c = wn + nt * 8 + tr;
            float2 o0 = make_float2(ac2[mt][nt][0] + b2s[c],
                                    ac2[mt][nt][1] + b2s[c + 1]);
            float2 o1 = make_float2(ac2[mt][nt][2] + b2s[c],
                                    ac2[mt][nt][3] + b2s[c + 1]);
            size_t i0 = (size_t)(row0 + r) * 128 + c;
            size_t i1 = (size_t)(row0 + r + 8) * 128 + c;
            *(float2*)(g_Vres + i0) = o0;
            *(float2*)(g_Vres + i1) = o1;
            u32 hs0 = f32_to_h2(o0.x * F8_SCALE, o0.y * F8_SCALE);
            u32 hs1 = f32_to_h2(o1.x * F8_SCALE, o1.y * F8_SCALE);
            *(u16*)(g_Vf8r + i0) = h2_to_f8(hs0);
            *(u16*)(g_Vf8r + i1) = h2_to_f8(hs1);
        }
}

// ---------------------------------------------------------------------------
// k_mlp_f: f-nets (single-term bf16). Compact smem (~70 KB) -> 2 CTAs/SM.
// grid = (128 row-tiles, 12 nets), 512 threads.
// ---------------------------------------------------------------------------
#define F_W1HI  0
#define F_XHHI  32768
#define F_F2HI  65536
#define F_B1S   69632
#define F_B2S   70144
#define SMEM_F  70656

__global__ void __launch_bounds__(512, 2) k_mlp_f(
    const float* __restrict__ fb1, const float* __restrict__ fb2) {
    const int tid = threadIdx.x;
    const int lane = tid & 31;
    const int wid = tid >> 5;
    const int m = blockIdx.y;               // 0..11 (f-net index)
    const int row0 = blockIdx.x * 128;
    const u32 sbase = smem_u32(smc);
    float* b1s = (float*)(smc + F_B1S);
    float* b2s = (float*)(smc + F_B2S);

    {
        const uint4* s1h = (const uint4*)g_B1hi + (m + 1) * 2048;
        const uint4* sxh = (const uint4*)g_Xhi + row0 * 16;
        #pragma unroll
        for (int p = 0; p < 4; ++p) {
            int q = tid + p * 512;
            int r = q >> 4, c16 = q & 15;
            u32 d = (u32)(((r << 4) + (c16 ^ (r & 7))) << 4);
            *(uint4*)(smc + F_W1HI + d) = s1h[q];
            *(uint4*)(smc + F_XHHI + d) = sxh[q];
        }
    }
    {
        const uint4* sfh = (const uint4*)g_B2fhi + m * 256;
        if (tid < 256) {
            int r = tid >> 4, c16 = tid & 15;
            u32 d = (u32)(((r << 4) + (c16 ^ (r & 7))) << 4);
            *(uint4*)(smc + F_F2HI + d) = sfh[tid];
        }
        if (tid < 128) b1s[tid] = fb1[m * 128 + tid];
        if (tid < 16)  b2s[tid] = (tid < 13) ? fb2[m * 13 + tid] : 0.0f;
    }
    __syncthreads();

    const int a_ro = (lane & 7) + (lane & 8);
    const int a_co = lane >> 4;
    const int b_ro = (lane & 7) + ((lane >> 1) & 8);
    const int b_co = (lane >> 3) & 1;
    const int tq = lane >> 2;
    const int tr = (lane & 3) * 2;
    const int wm = (wid & 3) * 32;
    const int wn = (wid >> 2) * 32;

    // Layer 1 (single term)
    float acc[2][4][4];
    #pragma unroll
    for (int i = 0; i < 2; ++i)
        #pragma unroll
        for (int j = 0; j < 4; ++j)
            #pragma unroll
            for (int q = 0; q < 4; ++q) acc[i][j][q] = 0.0f;
    #pragma unroll
    for (int k = 0; k < 8; ++k) {
        const int kc = k * 2;
        u32 ah[2][4], bh[2][4];
        #pragma unroll
        for (int mt = 0; mt < 2; ++mt)
            ldsm4(ah[mt], sw_addr(sbase + F_XHHI, wm + mt * 16 + a_ro, kc + a_co));
        #pragma unroll
        for (int ng = 0; ng < 2; ++ng)
            ldsm4(bh[ng], sw_addr(sbase + F_W1HI, wn + ng * 16 + b_ro, kc + b_co));
        #pragma unroll
        for (int mt = 0; mt < 2; ++mt)
            #pragma unroll
            for (int ng = 0; ng < 2; ++ng) {
                mma16816(acc[mt][2 * ng],     ah[mt], &bh[ng][0]);
                mma16816(acc[mt][2 * ng + 1], ah[mt], &bh[ng][2]);
            }
    }
    __syncthreads();

    // epilogue 1: bias + gelu -> H (bf16) over X region
    #pragma unroll
    for (int mt = 0; mt < 2; ++mt)
        #pragma unroll
        for (int nt = 0; nt < 4; ++nt) {
            int r = wm + mt * 16 + tq;
            int c = wn + nt * 8 + tr;
            float v0 = gelu_exact(acc[mt][nt][0] + b1s[c]);
            float v1 = gelu_exact(acc[mt][nt][1] + b1s[c + 1]);
            float v2 = gelu_exact(acc[mt][nt][2] + b1s[c]);
            float v3 = gelu_exact(acc[mt][nt][3] + b1s[c + 1]);
            int c16 = c >> 3, cb = (c & 7) * 2;
            u32 d0 = sw_addr(sbase + F_XHHI, r, c16) - sbase + cb;
            u32 d8 = sw_addr(sbase + F_XHHI, r + 8, c16) - sbase + cb;
            *(u32*)(smc + d0) = pack_bf16x2(v0, v1);
            *(u32*)(smc + d8) = pack_bf16x2(v2, v3);
        }
    __syncthreads();

    // Layer 2: W_all = H @ fW2 (N=16 padded), warps 0-7
    if (wid < 8) {
        const int wm2 = wid * 16;
        float ac2[2][4];
        #pragma unroll
        for (int j = 0; j < 2; ++j)
            #pragma unroll
            for (int q = 0; q < 4; ++q) ac2[j][q] = 0.0f;
        #pragma unroll
        for (int k = 0; k < 8; ++k) {
            const int kc = k * 2;
            u32 ah[4], bh[4];
            ldsm4(ah, sw_addr(sbase + F_XHHI, wm2 + a_ro, kc + a_co));
            ldsm4(bh, sw_addr(sbase + F_F2HI, b_ro, kc + b_co));
            mma16816(ac2[0], ah, &bh[0]);
            mma16816(ac2[1], ah, &bh[2]);
        }
        float* op = g_Wall + (size_t)m * R_TOT * K_LNK + (size_t)row0 * K_LNK;
        #pragma unroll
        for (int nt = 0; nt < 2; ++nt) {
            int c = nt * 8 + tr;
            int r = wm2 + tq;
            if (c < 13) {
                op[(r) * K_LNK + c]     = ac2[nt][0] + b2s[c];
                op[(r + 8) * K_LNK + c] = ac2[nt][2] + b2s[c];
            }
            if (c + 1 < 13) {
                op[(r) * K_LNK + c + 1]     = ac2[nt][1] + b2s[c + 1];
                op[(r + 8) * K_LNK + c + 1] = ac2[nt][3] + b2s[c + 1];
            }
        }
    }
}

// ---------------------------------------------------------------------------
// k_scan: chord-mix step, fp8 gathers, f16x2 accum. 128-thread blocks,
// launch_bounds(128, 12) -> 1536 thr/SM; gather batches 5+4+4 (~40 regs).
// ---------------------------------------------------------------------------
__global__ void __launch_bounds__(128, 12) k_scan(int m, const int* __restrict__ cols,
                                                  float* __restrict__ out_final) {
    const u8* Vin = (m == 0) ? g_Vf8r : ((m & 1) ? g_Vf8b : g_Vf8a);
    u8* Vout = (m & 1) ? g_Vf8a : g_Vf8b;
    const float* Wm = g_Wall + (size_t)m * R_TOT * K_LNK;

    const int lane = threadIdx.x & 31;
    const int pair = (blockIdx.x * blockDim.x + threadIdx.x) >> 5;
    const int hl   = lane & 15;
    const int lr   = pair * 2 + (lane >> 4);

    u32 wv = 0; int iv = 0;
    if (hl < K_LNK) {
        float w = Wm[lr * K_LNK + hl];
        wv = f32_to_h2(w, w);
        int s = lr & (S_LEN - 1), b = lr >> 12;
        iv = ((b << 12) | cols[s * K_LNK + hl]) << 4;  // uint2 row base (16/row)
    }

    const uint2* Vin2 = (const uint2*)Vin;
    u32 a0 = 0, a1 = 0, a2 = 0, a3 = 0;     // f16x2 mix accumulators (*256)
    const int selk = lane & 16;

    #pragma unroll
    for (int base = 0; base < K_LNK; base += 5) {
        const int nb = (base == 0) ? 5 : 4;
        u32 wk[5]; uint2 v[5];
        #pragma unroll
        for (int j = 0; j < 5; ++j) {
            if (j < nb) {
                wk[j] = __shfl_sync(0xffffffffu, wv, (base + j) | selk);
                int ik = __shfl_sync(0xffffffffu, iv, (base + j) | selk);
                v[j] = Vin2[ik + hl];
            }
        }
        #pragma unroll
        for (int j = 0; j < 5; ++j) {
            if (j < nb) {
                u32 h0, h1, h2, h3;
                f8_to_h2(v[j].x, h0, h1);
                f8_to_h2(v[j].y, h2, h3);
                hfma2(a0, h0, wk[j]);
                hfma2(a1, h1, wk[j]);
                hfma2(a2, h2, wk[j]);
                hfma2(a3, h3, wk[j]);
            }
        }
    }

    if (m == M_NET - 1) {
        const float4* res4 = (const float4*)g_Vres + ((size_t)lr << 5);
        float4 r0 = res4[hl * 2], r1 = res4[hl * 2 + 1];
        float2 f0 = __half22float2(*(__half2*)&a0);
        float2 f1 = __half22float2(*(__half2*)&a1);
        float2 f2 = __half22float2(*(__half2*)&a2);
        float2 f3 = __half22float2(*(__half2*)&a3);
        r0.x += f0.x * F8_INV; r0.y += f0.y * F8_INV;
        r0.z += f1.x * F8_INV; r0.w += f1.y * F8_INV;
        r1.x += f2.x * F8_INV; r1.y += f2.y * F8_INV;
        r1.z += f3.x * F8_INV; r1.w += f3.y * F8_INV;
        float4* op = (float4*)out_final + ((size_t)lr << 5);
        op[hl * 2]     = r0;
        op[hl * 2 + 1] = r1;
    } else {
        uint2 rr = ((const uint2*)g_Vf8r)[((size_t)lr << 4) + hl];
        u32 r0, r1, r2, r3;
        f8_to_h2(rr.x, r0, r1);
        f8_to_h2(rr.y, r2, r3);
        u16 s0 = h2_to_f8(hadd2(r0, a0));
        u16 s1 = h2_to_f8(hadd2(r1, a1));
        u16 s2 = h2_to_f8(hadd2(r2, a2));
        u16 s3 = h2_to_f8(hadd2(r3, a3));
        uint2 ov;
        ov.x = pack_u16x2(s0, s1);
        ov.y = pack_u16x2(s2, s3);
        ((uint2*)Vout)[((size_t)lr << 4) + hl] = ov;
    }
}

// ---------------------------------------------------------------------------
extern "C" void kernel_launch(void* const* d_in, const int* in_sizes, int n_in,
                              void* d_out, int out_size) {
    const int*   data = (const int*)  d_in[0];
    const int*   cols = (const int*)  d_in[1];
    const float* emb  = (const float*)d_in[2];
    const float* apc  = (const float*)d_in[3];
    const float* gW1  = (const float*)d_in[4];
    const float* gb1  = (const float*)d_in[5];
    const float* gW2  = (const float*)d_in[6];
    const float* gb2  = (const float*)d_in[7];
    const float* fW1  = (const float*)d_in[8];
    const float* fb1  = (const float*)d_in[9];
    const float* fW2  = (const float*)d_in[10];
    const float* fb2  = (const float*)d_in[11];
    float* out = (float*)d_out;

    cudaFuncSetAttribute(k_mlp_g, cudaFuncAttributeMaxDynamicSharedMemorySize,
                         SMEM_G);
    cudaFuncSetAttribute(k_mlp_f, cudaFuncAttributeMaxDynamicSharedMemorySize,
                         SMEM_F);

    // 1) weight prep (coalesced smem transpose) + embeddings
    k_init<<<INIT_BLK, 256>>>(gW1, gW2, fW1, fW2, data, emb, apc);

    // 2) f-nets (2 CTAs/SM) then g-net (1 CTA/SM)
    dim3 grid_f(R_TOT / 128, 12);
    k_mlp_f<<<grid_f, 512, SMEM_F>>>(fb1, fb2);
    k_mlp_g<<<R_TOT / 128, 512, SMEM_G>>>(gb1, gb2);

    // 3) 12 chord-mix scan steps (fp8 gathers, 128-thr blocks, batches 5/4/4)
    for (int m = 0; m < M_NET; ++m)
        k_scan<<<R_TOT / 8, 128>>>(m, cols, out);
}